// round 9
// baseline (speedup 1.0000x reference)
#include <cuda_runtime.h>
#include <cuda_fp16.h>

#define N_NODES 100000
#define N_EDGES 1600000
#define IN_DIM  128
#define OUT_DIM 64
#define NEG_SLOPE 0.2f

#define SCAN_B 1024
#define SCAN_NB ((N_NODES + SCAN_B - 1) / SCAN_B)   // 98
#define GEMM_BLOCKS ((N_NODES + 63) / 64)           // 1563
#define HIST_BLOCKS ((N_EDGES / 4 + 255) / 256)     // 1563

// Scratch (static device globals — zero-init at load; g_count self-cleaning)
__device__ __align__(16) __half g_Whh[(size_t)N_NODES * OUT_DIM];
__device__ float g_ssrc[N_NODES];
__device__ float g_sdst[N_NODES];
__device__ int   g_count[N_NODES];     // agg zeroes after use
__device__ int   g_rowstart[N_NODES];
__device__ int   g_bsum[SCAN_NB];
__device__ int   g_eoff[N_EDGES];      // per-edge rank within its row
__device__ __align__(8) int2 g_epack[N_EDGES];   // (col, bits(w)) grouped by row

// ---------------------------------------------------------------------------
// K1: role-split. GEMM blocks: Wh = h@W fused with s_src/s_dst.
// Hist blocks: row histogram, recording each edge's within-row rank.
// ---------------------------------------------------------------------------
__global__ void gemm_hist_kernel(const float* __restrict__ h,
                                 const float* __restrict__ W,
                                 const float* __restrict__ a,
                                 const int*   __restrict__ row) {
    __shared__ __align__(16) float hs[64][68];
    __shared__ __align__(16) float Ws[64][64];

    const int tid = threadIdx.x;

    if (blockIdx.x >= GEMM_BLOCKS) {
        // ---- histogram role: 4 edges per thread, rank recorded ----
        int t = (blockIdx.x - GEMM_BLOCKS) * blockDim.x + tid;
        int e4 = t * 4;
        if (e4 + 3 < N_EDGES) {
            int4 r = ((const int4*)row)[t];
            int4 o;
            o.x = atomicAdd(&g_count[r.x], 1);
            o.y = atomicAdd(&g_count[r.y], 1);
            o.z = atomicAdd(&g_count[r.z], 1);
            o.w = atomicAdd(&g_count[r.w], 1);
            ((int4*)g_eoff)[t] = o;
        } else {
            for (int e = e4; e < N_EDGES; e++)
                g_eoff[e] = atomicAdd(&g_count[row[e]], 1);
        }
        return;
    }

    // ---- GEMM role ----
    const int tx   = tid & 15;
    const int ty   = tid >> 4;
    const int row0 = blockIdx.x * 64;

    float acc[4][4];
    #pragma unroll
    for (int i = 0; i < 4; i++)
        #pragma unroll
        for (int j = 0; j < 4; j++) acc[i][j] = 0.f;

    #pragma unroll
    for (int kc = 0; kc < 2; kc++) {
        #pragma unroll
        for (int p = 0; p < 4; p++) {
            int idx = tid + p * 256;
            int r = idx >> 4, c4 = idx & 15;
            int node = row0 + r;
            float4 v = make_float4(0.f, 0.f, 0.f, 0.f);
            if (node < N_NODES)
                v = ((const float4*)h)[(size_t)node * 32 + kc * 16 + c4];
            *(float4*)&hs[r][c4 * 4] = v;
        }
        #pragma unroll
        for (int p = 0; p < 4; p++) {
            int idx = tid + p * 256;
            int k = idx >> 4, n4 = idx & 15;
            *(float4*)&Ws[k][n4 * 4] =
                ((const float4*)W)[(size_t)(kc * 64 + k) * 16 + n4];
        }
        __syncthreads();

        #pragma unroll 8
        for (int k = 0; k < 64; k++) {
            float4 wv = *(const float4*)&Ws[k][tx * 4];
            float h0 = hs[ty * 4 + 0][k];
            float h1 = hs[ty * 4 + 1][k];
            float h2 = hs[ty * 4 + 2][k];
            float h3 = hs[ty * 4 + 3][k];
            acc[0][0] = fmaf(h0, wv.x, acc[0][0]);
            acc[0][1] = fmaf(h0, wv.y, acc[0][1]);
            acc[0][2] = fmaf(h0, wv.z, acc[0][2]);
            acc[0][3] = fmaf(h0, wv.w, acc[0][3]);
            acc[1][0] = fmaf(h1, wv.x, acc[1][0]);
            acc[1][1] = fmaf(h1, wv.y, acc[1][1]);
            acc[1][2] = fmaf(h1, wv.z, acc[1][2]);
            acc[1][3] = fmaf(h1, wv.w, acc[1][3]);
            acc[2][0] = fmaf(h2, wv.x, acc[2][0]);
            acc[2][1] = fmaf(h2, wv.y, acc[2][1]);
            acc[2][2] = fmaf(h2, wv.z, acc[2][2]);
            acc[2][3] = fmaf(h2, wv.w, acc[2][3]);
            acc[3][0] = fmaf(h3, wv.x, acc[3][0]);
            acc[3][1] = fmaf(h3, wv.y, acc[3][1]);
            acc[3][2] = fmaf(h3, wv.z, acc[3][2]);
            acc[3][3] = fmaf(h3, wv.w, acc[3][3]);
        }
        __syncthreads();
    }

    const float4 as = *(const float4*)&a[tx * 4];
    const float4 ad = *(const float4*)&a[64 + tx * 4];
    float ss[4], sd[4];
    #pragma unroll
    for (int i = 0; i < 4; i++) {
        int node = row0 + ty * 4 + i;
        if (node < N_NODES) {
            __half2 lo = __floats2half2_rn(acc[i][0], acc[i][1]);
            __half2 hi = __floats2half2_rn(acc[i][2], acc[i][3]);
            uint2 pk;
            pk.x = *(unsigned int*)&lo;
            pk.y = *(unsigned int*)&hi;
            ((uint2*)g_Whh)[(size_t)node * 16 + tx] = pk;
        }
        ss[i] = acc[i][0] * as.x + acc[i][1] * as.y + acc[i][2] * as.z + acc[i][3] * as.w;
        sd[i] = acc[i][0] * ad.x + acc[i][1] * ad.y + acc[i][2] * ad.z + acc[i][3] * ad.w;
    }
    #pragma unroll
    for (int o = 8; o > 0; o >>= 1) {
        #pragma unroll
        for (int i = 0; i < 4; i++) {
            ss[i] += __shfl_down_sync(0xFFFFFFFFu, ss[i], o, 16);
            sd[i] += __shfl_down_sync(0xFFFFFFFFu, sd[i], o, 16);
        }
    }
    if (tx == 0) {
        #pragma unroll
        for (int i = 0; i < 4; i++) {
            int node = row0 + ty * 4 + i;
            if (node < N_NODES) { g_ssrc[node] = ss[i]; g_sdst[node] = sd[i]; }
        }
    }
}

// ---------------------------------------------------------------------------
// K2: block-local exclusive scan of g_count -> g_rowstart, block sums in bsum
// ---------------------------------------------------------------------------
__global__ void scan1_kernel() {
    __shared__ int s[SCAN_B];
    int i = blockIdx.x * SCAN_B + threadIdx.x;
    int v = (i < N_NODES) ? g_count[i] : 0;
    s[threadIdx.x] = v;
    __syncthreads();
    int x = v;
    #pragma unroll
    for (int o = 1; o < SCAN_B; o <<= 1) {
        int t = (threadIdx.x >= o) ? s[threadIdx.x - o] : 0;
        __syncthreads();
        x += t;
        s[threadIdx.x] = x;
        __syncthreads();
    }
    if (i < N_NODES) g_rowstart[i] = x - v;
    if (threadIdx.x == SCAN_B - 1) g_bsum[blockIdx.x] = x;
}

// ---------------------------------------------------------------------------
// K3: add bsum prefix (per-block reduction) to rowstart
// ---------------------------------------------------------------------------
__global__ void scan3_kernel() {
    __shared__ int warp_part[4];
    __shared__ int s_prefix;
    const int b = blockIdx.x;
    const int t = threadIdx.x;

    if (t < 128) {
        int v = (t < b) ? g_bsum[t] : 0;     // b <= 97 < 128
        #pragma unroll
        for (int o = 16; o > 0; o >>= 1)
            v += __shfl_down_sync(0xFFFFFFFFu, v, o);
        if ((t & 31) == 0) warp_part[t >> 5] = v;
    }
    __syncthreads();
    if (t == 0)
        s_prefix = warp_part[0] + warp_part[1] + warp_part[2] + warp_part[3];
    __syncthreads();

    int i = b * SCAN_B + t;
    if (i < N_NODES)
        g_rowstart[i] += s_prefix;
}

// ---------------------------------------------------------------------------
// K4: per-edge weight + atomic-free scatter (position = rowstart + eoff)
// ---------------------------------------------------------------------------
__global__ void scatter_kernel(const int* __restrict__ row,
                               const int* __restrict__ col) {
    int t = blockIdx.x * blockDim.x + threadIdx.x;
    int e4 = t * 4;
    if (e4 + 3 < N_EDGES) {
        int4 r = ((const int4*)row)[t];
        int4 c = ((const int4*)col)[t];
        int4 o = ((const int4*)g_eoff)[t];
        #pragma unroll
        for (int j = 0; j < 4; j++) {
            int rr = (j == 0) ? r.x : (j == 1) ? r.y : (j == 2) ? r.z : r.w;
            int cc = (j == 0) ? c.x : (j == 1) ? c.y : (j == 2) ? c.z : c.w;
            int oo = (j == 0) ? o.x : (j == 1) ? o.y : (j == 2) ? o.z : o.w;
            float x = g_ssrc[rr] + g_sdst[cc];
            x = (x > 0.f) ? x : NEG_SLOPE * x;
            float w = __expf(x);
            g_epack[g_rowstart[rr] + oo] = make_int2(cc, __float_as_int(w));
        }
    } else {
        for (int e = e4; e < N_EDGES; e++) {
            int rr = row[e], cc = col[e];
            float x = g_ssrc[rr] + g_sdst[cc];
            x = (x > 0.f) ? x : NEG_SLOPE * x;
            float w = __expf(x);
            g_epack[g_rowstart[rr] + g_eoff[e]] = make_int2(cc, __float_as_int(w));
        }
    }
}

// ---------------------------------------------------------------------------
// K5: single-pass per-node aggregation. Accumulate unnormalized w*Wh and
// per-lane w-sum simultaneously; scale by 1/denom at the end.
// ---------------------------------------------------------------------------
__global__ void agg_csr_kernel(float* __restrict__ out) {
    const int warp = (blockIdx.x * blockDim.x + threadIdx.x) >> 5;
    const int lane = threadIdx.x & 31;
    if (warp >= N_NODES) return;

    const int start = g_rowstart[warp];
    const int cnt   = g_count[warp];

    const int half = lane >> 4;      // 0: even edges, 1: odd edges
    const int hl   = lane & 15;      // column group within half

    const uint2* Wh4 = (const uint2*)g_Whh;
    float4 acc = make_float4(0.f, 0.f, 0.f, 0.f);
    float dsum = 0.f;

    for (int base = 0; base < cnt; base += 32) {
        int idx = base + lane;
        int2 p = (idx < cnt) ? __ldg(&g_epack[start + idx]) : make_int2(0, 0);
        float w_lane = __int_as_float(p.y);          // 0 for padding
        dsum += w_lane;
        int m = cnt - base; if (m > 32) m = 32;
        int nsteps = (m + 1) >> 1;
        #pragma unroll 4
        for (int j = 0; j < nsteps; j++) {
            int src = 2 * j + half;                  // padded lane has w=0
            int   c = __shfl_sync(0xFFFFFFFFu, p.x, src);
            float w = __shfl_sync(0xFFFFFFFFu, w_lane, src);
            uint2 raw = __ldg(&Wh4[(size_t)c * 16 + hl]);
            float2 v0 = __half22float2(*(const __half2*)&raw.x);
            float2 v1 = __half22float2(*(const __half2*)&raw.y);
            acc.x = fmaf(w, v0.x, acc.x);
            acc.y = fmaf(w, v0.y, acc.y);
            acc.z = fmaf(w, v1.x, acc.z);
            acc.w = fmaf(w, v1.y, acc.w);
        }
    }

    // full-warp denominator
    #pragma unroll
    for (int o = 16; o > 0; o >>= 1)
        dsum += __shfl_xor_sync(0xFFFFFFFFu, dsum, o);
    const float inv = 1.f / (dsum + 1e-10f);

    // combine even/odd partials, scale, write
    acc.x += __shfl_xor_sync(0xFFFFFFFFu, acc.x, 16);
    acc.y += __shfl_xor_sync(0xFFFFFFFFu, acc.y, 16);
    acc.z += __shfl_xor_sync(0xFFFFFFFFu, acc.z, 16);
    acc.w += __shfl_xor_sync(0xFFFFFFFFu, acc.w, 16);

    if (half == 0) {
        acc.x *= inv; acc.y *= inv; acc.z *= inv; acc.w *= inv;
        ((float4*)out)[(size_t)warp * 16 + hl] = acc;
    }

    if (lane == 0) g_count[warp] = 0;   // self-clean for next replay
}

// ---------------------------------------------------------------------------
extern "C" void kernel_launch(void* const* d_in, const int* in_sizes, int n_in,
                              void* d_out, int out_size) {
    const float* h   = (const float*)d_in[0];
    const int*   row = (const int*)d_in[1];
    const int*   col = (const int*)d_in[2];
    const float* W   = (const float*)d_in[3];
    const float* a   = (const float*)d_in[4];
    float*       out = (float*)d_out;

    gemm_hist_kernel<<<GEMM_BLOCKS + HIST_BLOCKS, 256>>>(h, W, a, row);
    scan1_kernel<<<SCAN_NB, SCAN_B>>>();
    scan3_kernel<<<SCAN_NB, SCAN_B>>>();
    scatter_kernel<<<HIST_BLOCKS, 256>>>(row, col);
    agg_csr_kernel<<<(N_NODES * 32 + 255) / 256, 256>>>(out);
}

// round 10
// speedup vs baseline: 1.0335x; 1.0335x over previous
#include <cuda_runtime.h>
#include <cuda_fp16.h>

#define N_NODES 100000
#define N_EDGES 1600000
#define IN_DIM  128
#define OUT_DIM 64
#define NEG_SLOPE 0.2f

#define SCAN_B 1024
#define SCAN_NB ((N_NODES + SCAN_B - 1) / SCAN_B)   // 98
#define GEMM_BLOCKS ((N_NODES + 63) / 64)           // 1563
#define HIST_BLOCKS ((N_EDGES / 4 + 255) / 256)     // 1563

// Scratch (static device globals — zero-init at load; g_count self-cleaning)
__device__ __align__(16) __half g_Whh[(size_t)N_NODES * OUT_DIM];
__device__ float g_ssrc[N_NODES];
__device__ float g_sdst[N_NODES];
__device__ int   g_count[N_NODES];     // agg zeroes after use
__device__ int   g_rowstart[N_NODES];
__device__ int   g_cursor[N_NODES];
__device__ int   g_bsum[SCAN_NB];
__device__ int   g_ecol[N_EDGES];      // col indices grouped by row

// ---------------------------------------------------------------------------
// K1: role-split. GEMM blocks: Wh = h@W fused with s_src/s_dst.
// Hist blocks: pure row histogram (R8 form — no rank recording).
// ---------------------------------------------------------------------------
__global__ void gemm_hist_kernel(const float* __restrict__ h,
                                 const float* __restrict__ W,
                                 const float* __restrict__ a,
                                 const int*   __restrict__ row) {
    __shared__ __align__(16) float hs[64][68];
    __shared__ __align__(16) float Ws[64][64];

    const int tid = threadIdx.x;

    if (blockIdx.x >= GEMM_BLOCKS) {
        int t = (blockIdx.x - GEMM_BLOCKS) * blockDim.x + tid;
        int e4 = t * 4;
        if (e4 + 3 < N_EDGES) {
            int4 r = ((const int4*)row)[t];
            atomicAdd(&g_count[r.x], 1);
            atomicAdd(&g_count[r.y], 1);
            atomicAdd(&g_count[r.z], 1);
            atomicAdd(&g_count[r.w], 1);
        } else {
            for (int e = e4; e < N_EDGES; e++) atomicAdd(&g_count[row[e]], 1);
        }
        return;
    }

    // ---- GEMM role ----
    const int tx   = tid & 15;
    const int ty   = tid >> 4;
    const int row0 = blockIdx.x * 64;

    float acc[4][4];
    #pragma unroll
    for (int i = 0; i < 4; i++)
        #pragma unroll
        for (int j = 0; j < 4; j++) acc[i][j] = 0.f;

    #pragma unroll
    for (int kc = 0; kc < 2; kc++) {
        #pragma unroll
        for (int p = 0; p < 4; p++) {
            int idx = tid + p * 256;
            int r = idx >> 4, c4 = idx & 15;
            int node = row0 + r;
            float4 v = make_float4(0.f, 0.f, 0.f, 0.f);
            if (node < N_NODES)
                v = ((const float4*)h)[(size_t)node * 32 + kc * 16 + c4];
            *(float4*)&hs[r][c4 * 4] = v;
        }
        #pragma unroll
        for (int p = 0; p < 4; p++) {
            int idx = tid + p * 256;
            int k = idx >> 4, n4 = idx & 15;
            *(float4*)&Ws[k][n4 * 4] =
                ((const float4*)W)[(size_t)(kc * 64 + k) * 16 + n4];
        }
        __syncthreads();

        #pragma unroll 8
        for (int k = 0; k < 64; k++) {
            float4 wv = *(const float4*)&Ws[k][tx * 4];
            float h0 = hs[ty * 4 + 0][k];
            float h1 = hs[ty * 4 + 1][k];
            float h2 = hs[ty * 4 + 2][k];
            float h3 = hs[ty * 4 + 3][k];
            acc[0][0] = fmaf(h0, wv.x, acc[0][0]);
            acc[0][1] = fmaf(h0, wv.y, acc[0][1]);
            acc[0][2] = fmaf(h0, wv.z, acc[0][2]);
            acc[0][3] = fmaf(h0, wv.w, acc[0][3]);
            acc[1][0] = fmaf(h1, wv.x, acc[1][0]);
            acc[1][1] = fmaf(h1, wv.y, acc[1][1]);
            acc[1][2] = fmaf(h1, wv.z, acc[1][2]);
            acc[1][3] = fmaf(h1, wv.w, acc[1][3]);
            acc[2][0] = fmaf(h2, wv.x, acc[2][0]);
            acc[2][1] = fmaf(h2, wv.y, acc[2][1]);
            acc[2][2] = fmaf(h2, wv.z, acc[2][2]);
            acc[2][3] = fmaf(h2, wv.w, acc[2][3]);
            acc[3][0] = fmaf(h3, wv.x, acc[3][0]);
            acc[3][1] = fmaf(h3, wv.y, acc[3][1]);
            acc[3][2] = fmaf(h3, wv.z, acc[3][2]);
            acc[3][3] = fmaf(h3, wv.w, acc[3][3]);
        }
        __syncthreads();
    }

    const float4 as = *(const float4*)&a[tx * 4];
    const float4 ad = *(const float4*)&a[64 + tx * 4];
    float ss[4], sd[4];
    #pragma unroll
    for (int i = 0; i < 4; i++) {
        int node = row0 + ty * 4 + i;
        if (node < N_NODES) {
            __half2 lo = __floats2half2_rn(acc[i][0], acc[i][1]);
            __half2 hi = __floats2half2_rn(acc[i][2], acc[i][3]);
            uint2 pk;
            pk.x = *(unsigned int*)&lo;
            pk.y = *(unsigned int*)&hi;
            ((uint2*)g_Whh)[(size_t)node * 16 + tx] = pk;
        }
        ss[i] = acc[i][0] * as.x + acc[i][1] * as.y + acc[i][2] * as.z + acc[i][3] * as.w;
        sd[i] = acc[i][0] * ad.x + acc[i][1] * ad.y + acc[i][2] * ad.z + acc[i][3] * ad.w;
    }
    #pragma unroll
    for (int o = 8; o > 0; o >>= 1) {
        #pragma unroll
        for (int i = 0; i < 4; i++) {
            ss[i] += __shfl_down_sync(0xFFFFFFFFu, ss[i], o, 16);
            sd[i] += __shfl_down_sync(0xFFFFFFFFu, sd[i], o, 16);
        }
    }
    if (tx == 0) {
        #pragma unroll
        for (int i = 0; i < 4; i++) {
            int node = row0 + ty * 4 + i;
            if (node < N_NODES) { g_ssrc[node] = ss[i]; g_sdst[node] = sd[i]; }
        }
    }
}

// ---------------------------------------------------------------------------
// K2: block-local exclusive scan of g_count -> g_rowstart, block sums in bsum
// ---------------------------------------------------------------------------
__global__ void scan1_kernel() {
    __shared__ int s[SCAN_B];
    int i = blockIdx.x * SCAN_B + threadIdx.x;
    int v = (i < N_NODES) ? g_count[i] : 0;
    s[threadIdx.x] = v;
    __syncthreads();
    int x = v;
    #pragma unroll
    for (int o = 1; o < SCAN_B; o <<= 1) {
        int t = (threadIdx.x >= o) ? s[threadIdx.x - o] : 0;
        __syncthreads();
        x += t;
        s[threadIdx.x] = x;
        __syncthreads();
    }
    if (i < N_NODES) g_rowstart[i] = x - v;
    if (threadIdx.x == SCAN_B - 1) g_bsum[blockIdx.x] = x;
}

// ---------------------------------------------------------------------------
// K3: add bsum prefix to rowstart + init cursor
// ---------------------------------------------------------------------------
__global__ void scan3_kernel() {
    __shared__ int warp_part[4];
    __shared__ int s_prefix;
    const int b = blockIdx.x;
    const int t = threadIdx.x;

    if (t < 128) {
        int v = (t < b) ? g_bsum[t] : 0;     // b <= 97 < 128
        #pragma unroll
        for (int o = 16; o > 0; o >>= 1)
            v += __shfl_down_sync(0xFFFFFFFFu, v, o);
        if ((t & 31) == 0) warp_part[t >> 5] = v;
    }
    __syncthreads();
    if (t == 0)
        s_prefix = warp_part[0] + warp_part[1] + warp_part[2] + warp_part[3];
    __syncthreads();

    int i = b * SCAN_B + t;
    if (i < N_NODES) {
        int v = g_rowstart[i] + s_prefix;
        g_rowstart[i] = v;
        g_cursor[i]   = v;
    }
}

// ---------------------------------------------------------------------------
// K4: pure integer permutation: ecol[cursor[r]++] = c. 8 edges/thread.
// No score gathers, no exp — those moved into agg.
// ---------------------------------------------------------------------------
__global__ void scatter_kernel(const int* __restrict__ row,
                               const int* __restrict__ col) {
    int t = blockIdx.x * blockDim.x + threadIdx.x;
    int e8 = t * 8;
    if (e8 + 7 < N_EDGES) {
        int4 r0 = ((const int4*)row)[2 * t];
        int4 r1 = ((const int4*)row)[2 * t + 1];
        int4 c0 = ((const int4*)col)[2 * t];
        int4 c1 = ((const int4*)col)[2 * t + 1];
        int rr[8] = {r0.x, r0.y, r0.z, r0.w, r1.x, r1.y, r1.z, r1.w};
        int cc[8] = {c0.x, c0.y, c0.z, c0.w, c1.x, c1.y, c1.z, c1.w};
        #pragma unroll
        for (int j = 0; j < 8; j++) {
            int p = atomicAdd(&g_cursor[rr[j]], 1);
            g_ecol[p] = cc[j];
        }
    } else {
        for (int e = e8; e < N_EDGES; e++) {
            int p = atomicAdd(&g_cursor[row[e]], 1);
            g_ecol[p] = col[e];
        }
    }
}

// ---------------------------------------------------------------------------
// K5: single-pass per-node aggregation. ssrc[row] is warp-uniform; each lane
// computes its edge's weight from sdst[col], then the usual broadcast loop
// over fp16 Wh gathers. Unnormalized accumulation, scaled by 1/denom at end.
// ---------------------------------------------------------------------------
__global__ void agg_csr_kernel(float* __restrict__ out) {
    const int warp = (blockIdx.x * blockDim.x + threadIdx.x) >> 5;
    const int lane = threadIdx.x & 31;
    if (warp >= N_NODES) return;

    const int start = g_rowstart[warp];
    const int cnt   = g_count[warp];
    const float ssr = g_ssrc[warp];

    const int half = lane >> 4;      // 0: even edges, 1: odd edges
    const int hl   = lane & 15;      // column group within half

    const uint2* Wh4 = (const uint2*)g_Whh;
    float4 acc = make_float4(0.f, 0.f, 0.f, 0.f);
    float dsum = 0.f;

    for (int base = 0; base < cnt; base += 32) {
        int idx = base + lane;
        int c_lane = 0;
        float w_lane = 0.f;
        if (idx < cnt) {
            c_lane = __ldg(&g_ecol[start + idx]);
            float x = ssr + __ldg(&g_sdst[c_lane]);
            x = (x > 0.f) ? x : NEG_SLOPE * x;
            w_lane = __expf(x);
        }
        dsum += w_lane;
        int m = cnt - base; if (m > 32) m = 32;
        int nsteps = (m + 1) >> 1;
        #pragma unroll 4
        for (int j = 0; j < nsteps; j++) {
            int src = 2 * j + half;                  // padded lane has w=0
            int   c = __shfl_sync(0xFFFFFFFFu, c_lane, src);
            float w = __shfl_sync(0xFFFFFFFFu, w_lane, src);
            uint2 raw = __ldg(&Wh4[(size_t)c * 16 + hl]);
            float2 v0 = __half22float2(*(const __half2*)&raw.x);
            float2 v1 = __half22float2(*(const __half2*)&raw.y);
            acc.x = fmaf(w, v0.x, acc.x);
            acc.y = fmaf(w, v0.y, acc.y);
            acc.z = fmaf(w, v1.x, acc.z);
            acc.w = fmaf(w, v1.y, acc.w);
        }
    }

    #pragma unroll
    for (int o = 16; o > 0; o >>= 1)
        dsum += __shfl_xor_sync(0xFFFFFFFFu, dsum, o);
    const float inv = 1.f / (dsum + 1e-10f);

    acc.x += __shfl_xor_sync(0xFFFFFFFFu, acc.x, 16);
    acc.y += __shfl_xor_sync(0xFFFFFFFFu, acc.y, 16);
    acc.z += __shfl_xor_sync(0xFFFFFFFFu, acc.z, 16);
    acc.w += __shfl_xor_sync(0xFFFFFFFFu, acc.w, 16);

    if (half == 0) {
        acc.x *= inv; acc.y *= inv; acc.z *= inv; acc.w *= inv;
        ((float4*)out)[(size_t)warp * 16 + hl] = acc;
    }

    if (lane == 0) g_count[warp] = 0;   // self-clean for next replay
}

// ---------------------------------------------------------------------------
extern "C" void kernel_launch(void* const* d_in, const int* in_sizes, int n_in,
                              void* d_out, int out_size) {
    const float* h   = (const float*)d_in[0];
    const int*   row = (const int*)d_in[1];
    const int*   col = (const int*)d_in[2];
    const float* W   = (const float*)d_in[3];
    const float* a   = (const float*)d_in[4];
    float*       out = (float*)d_out;

    gemm_hist_kernel<<<GEMM_BLOCKS + HIST_BLOCKS, 256>>>(h, W, a, row);
    scan1_kernel<<<SCAN_NB, SCAN_B>>>();
    scan3_kernel<<<SCAN_NB, SCAN_B>>>();
    scatter_kernel<<<(N_EDGES / 8 + 255) / 256, 256>>>(row, col);
    agg_csr_kernel<<<(N_NODES * 32 + 255) / 256, 256>>>(out);
}

// round 12
// speedup vs baseline: 1.0469x; 1.0129x over previous
#include <cuda_runtime.h>
#include <cuda_fp16.h>

#define N_NODES 100000
#define N_EDGES 1600000
#define IN_DIM  128
#define OUT_DIM 64
#define NEG_SLOPE 0.2f

#define SCAN_B 1024
#define SCAN_NB ((N_NODES + SCAN_B - 1) / SCAN_B)   // 98
#define GEMM_BLOCKS ((N_NODES + 63) / 64)           // 1563
#define HIST_BLOCKS ((N_EDGES / 4 + 255) / 256)     // 1563

// Scratch (static device globals — zero-init at load; g_count self-cleaning)
__device__ __align__(16) __half g_Whh[(size_t)N_NODES * OUT_DIM];
__device__ float g_ssrc[N_NODES];
__device__ float g_sdst[N_NODES];
__device__ int   g_count[N_NODES];     // agg zeroes after use
__device__ int   g_rowstart[N_NODES];
__device__ int   g_bsum[SCAN_NB];
__device__ __align__(8) unsigned short g_eoff[N_EDGES];  // within-row rank (<= ~60)
__device__ int   g_ecol[N_EDGES];      // col indices grouped by row

// ---------------------------------------------------------------------------
// K1: role-split. GEMM blocks: Wh = h@W fused with s_src/s_dst.
// Hist blocks: row histogram + within-row rank (uint16), hidden under GEMM.
// ---------------------------------------------------------------------------
__global__ void gemm_hist_kernel(const float* __restrict__ h,
                                 const float* __restrict__ W,
                                 const float* __restrict__ a,
                                 const int*   __restrict__ row) {
    __shared__ __align__(16) float hs[64][68];
    __shared__ __align__(16) float Ws[64][64];

    const int tid = threadIdx.x;

    if (blockIdx.x >= GEMM_BLOCKS) {
        // ---- histogram + rank role: 4 edges per thread ----
        int t = (blockIdx.x - GEMM_BLOCKS) * blockDim.x + tid;
        int e4 = t * 4;
        if (e4 + 3 < N_EDGES) {
            int4 r = ((const int4*)row)[t];
            unsigned int o0 = (unsigned int)atomicAdd(&g_count[r.x], 1);
            unsigned int o1 = (unsigned int)atomicAdd(&g_count[r.y], 1);
            unsigned int o2 = (unsigned int)atomicAdd(&g_count[r.z], 1);
            unsigned int o3 = (unsigned int)atomicAdd(&g_count[r.w], 1);
            uint2 pk;
            pk.x = (o0 & 0xFFFFu) | (o1 << 16);
            pk.y = (o2 & 0xFFFFu) | (o3 << 16);
            ((uint2*)g_eoff)[t] = pk;            // 4 ushorts, 8B aligned
        } else {
            for (int e = e4; e < N_EDGES; e++)
                g_eoff[e] = (unsigned short)atomicAdd(&g_count[row[e]], 1);
        }
        return;
    }

    // ---- GEMM role ----
    const int tx   = tid & 15;
    const int ty   = tid >> 4;
    const int row0 = blockIdx.x * 64;

    float acc[4][4];
    #pragma unroll
    for (int i = 0; i < 4; i++)
        #pragma unroll
        for (int j = 0; j < 4; j++) acc[i][j] = 0.f;

    #pragma unroll
    for (int kc = 0; kc < 2; kc++) {
        #pragma unroll
        for (int p = 0; p < 4; p++) {
            int idx = tid + p * 256;
            int r = idx >> 4, c4 = idx & 15;
            int node = row0 + r;
            float4 v = make_float4(0.f, 0.f, 0.f, 0.f);
            if (node < N_NODES)
                v = ((const float4*)h)[(size_t)node * 32 + kc * 16 + c4];
            *(float4*)&hs[r][c4 * 4] = v;
        }
        #pragma unroll
        for (int p = 0; p < 4; p++) {
            int idx = tid + p * 256;
            int k = idx >> 4, n4 = idx & 15;
            *(float4*)&Ws[k][n4 * 4] =
                ((const float4*)W)[(size_t)(kc * 64 + k) * 16 + n4];
        }
        __syncthreads();

        #pragma unroll 8
        for (int k = 0; k < 64; k++) {
            float4 wv = *(const float4*)&Ws[k][tx * 4];
            float h0 = hs[ty * 4 + 0][k];
            float h1 = hs[ty * 4 + 1][k];
            float h2 = hs[ty * 4 + 2][k];
            float h3 = hs[ty * 4 + 3][k];
            acc[0][0] = fmaf(h0, wv.x, acc[0][0]);
            acc[0][1] = fmaf(h0, wv.y, acc[0][1]);
            acc[0][2] = fmaf(h0, wv.z, acc[0][2]);
            acc[0][3] = fmaf(h0, wv.w, acc[0][3]);
            acc[1][0] = fmaf(h1, wv.x, acc[1][0]);
            acc[1][1] = fmaf(h1, wv.y, acc[1][1]);
            acc[1][2] = fmaf(h1, wv.z, acc[1][2]);
            acc[1][3] = fmaf(h1, wv.w, acc[1][3]);
            acc[2][0] = fmaf(h2, wv.x, acc[2][0]);
            acc[2][1] = fmaf(h2, wv.y, acc[2][1]);
            acc[2][2] = fmaf(h2, wv.z, acc[2][2]);
            acc[2][3] = fmaf(h2, wv.w, acc[2][3]);
            acc[3][0] = fmaf(h3, wv.x, acc[3][0]);
            acc[3][1] = fmaf(h3, wv.y, acc[3][1]);
            acc[3][2] = fmaf(h3, wv.z, acc[3][2]);
            acc[3][3] = fmaf(h3, wv.w, acc[3][3]);
        }
        __syncthreads();
    }

    const float4 as = *(const float4*)&a[tx * 4];
    const float4 ad = *(const float4*)&a[64 + tx * 4];
    float ss[4], sd[4];
    #pragma unroll
    for (int i = 0; i < 4; i++) {
        int node = row0 + ty * 4 + i;
        if (node < N_NODES) {
            __half2 lo = __floats2half2_rn(acc[i][0], acc[i][1]);
            __half2 hi = __floats2half2_rn(acc[i][2], acc[i][3]);
            uint2 pk;
            pk.x = *(unsigned int*)&lo;
            pk.y = *(unsigned int*)&hi;
            ((uint2*)g_Whh)[(size_t)node * 16 + tx] = pk;
        }
        ss[i] = acc[i][0] * as.x + acc[i][1] * as.y + acc[i][2] * as.z + acc[i][3] * as.w;
        sd[i] = acc[i][0] * ad.x + acc[i][1] * ad.y + acc[i][2] * ad.z + acc[i][3] * ad.w;
    }
    #pragma unroll
    for (int o = 8; o > 0; o >>= 1) {
        #pragma unroll
        for (int i = 0; i < 4; i++) {
            ss[i] += __shfl_down_sync(0xFFFFFFFFu, ss[i], o, 16);
            sd[i] += __shfl_down_sync(0xFFFFFFFFu, sd[i], o, 16);
        }
    }
    if (tx == 0) {
        #pragma unroll
        for (int i = 0; i < 4; i++) {
            int node = row0 + ty * 4 + i;
            if (node < N_NODES) { g_ssrc[node] = ss[i]; g_sdst[node] = sd[i]; }
        }
    }
}

// ---------------------------------------------------------------------------
// K2: block-local exclusive scan of g_count -> g_rowstart, block sums in bsum
// ---------------------------------------------------------------------------
__global__ void scan1_kernel() {
    __shared__ int s[SCAN_B];
    int i = blockIdx.x * SCAN_B + threadIdx.x;
    int v = (i < N_NODES) ? g_count[i] : 0;
    s[threadIdx.x] = v;
    __syncthreads();
    int x = v;
    #pragma unroll
    for (int o = 1; o < SCAN_B; o <<= 1) {
        int t = (threadIdx.x >= o) ? s[threadIdx.x - o] : 0;
        __syncthreads();
        x += t;
        s[threadIdx.x] = x;
        __syncthreads();
    }
    if (i < N_NODES) g_rowstart[i] = x - v;
    if (threadIdx.x == SCAN_B - 1) g_bsum[blockIdx.x] = x;
}

// ---------------------------------------------------------------------------
// K3: add bsum prefix to rowstart
// ---------------------------------------------------------------------------
__global__ void scan3_kernel() {
    __shared__ int warp_part[4];
    __shared__ int s_prefix;
    const int b = blockIdx.x;
    const int t = threadIdx.x;

    if (t < 128) {
        int v = (t < b) ? g_bsum[t] : 0;     // b <= 97 < 128
        #pragma unroll
        for (int o = 16; o > 0; o >>= 1)
            v += __shfl_down_sync(0xFFFFFFFFu, v, o);
        if ((t & 31) == 0) warp_part[t >> 5] = v;
    }
    __syncthreads();
    if (t == 0)
        s_prefix = warp_part[0] + warp_part[1] + warp_part[2] + warp_part[3];
    __syncthreads();

    int i = b * SCAN_B + t;
    if (i < N_NODES)
        g_rowstart[i] += s_prefix;
}

// ---------------------------------------------------------------------------
// K4: atomic-free scatter: ecol[rowstart[r] + eoff[e]] = c. 8 edges/thread.
// One L2-resident gather (rowstart) + one random 4B store per edge; all
// loads independent -> deep MLP, unlike the atomic-return chain.
// ---------------------------------------------------------------------------
__global__ void scatter_kernel(const int* __restrict__ row,
                               const int* __restrict__ col) {
    int t = blockIdx.x * blockDim.x + threadIdx.x;
    int e8 = t * 8;
    if (e8 + 7 < N_EDGES) {
        int4 r0 = ((const int4*)row)[2 * t];
        int4 r1 = ((const int4*)row)[2 * t + 1];
        int4 c0 = ((const int4*)col)[2 * t];
        int4 c1 = ((const int4*)col)[2 * t + 1];
        uint2 ePk0 = ((const uint2*)g_eoff)[2 * t];
        uint2 ePk1 = ((const uint2*)g_eoff)[2 * t + 1];
        int rr[8] = {r0.x, r0.y, r0.z, r0.w, r1.x, r1.y, r1.z, r1.w};
        int cc[8] = {c0.x, c0.y, c0.z, c0.w, c1.x, c1.y, c1.z, c1.w};
        int oo[8] = {(int)(ePk0.x & 0xFFFFu), (int)(ePk0.x >> 16),
                     (int)(ePk0.y & 0xFFFFu), (int)(ePk0.y >> 16),
                     (int)(ePk1.x & 0xFFFFu), (int)(ePk1.x >> 16),
                     (int)(ePk1.y & 0xFFFFu), (int)(ePk1.y >> 16)};
        int st[8];
        #pragma unroll
        for (int j = 0; j < 8; j++) st[j] = __ldg(&g_rowstart[rr[j]]);
        #pragma unroll
        for (int j = 0; j < 8; j++) g_ecol[st[j] + oo[j]] = cc[j];
    } else {
        for (int e = e8; e < N_EDGES; e++)
            g_ecol[g_rowstart[row[e]] + (int)g_eoff[e]] = col[e];
    }
}

// ---------------------------------------------------------------------------
// K5: single-pass per-node aggregation. ssrc[row] warp-uniform; lanes compute
// weights from sdst[col]; broadcast loop over fp16 Wh gathers; normalize at end.
// ---------------------------------------------------------------------------
__global__ void agg_csr_kernel(float* __restrict__ out) {
    const int warp = (blockIdx.x * blockDim.x + threadIdx.x) >> 5;
    const int lane = threadIdx.x & 31;
    if (warp >= N_NODES) return;

    const int start = g_rowstart[warp];
    const int cnt   = g_count[warp];
    const float ssr = g_ssrc[warp];

    const int half = lane >> 4;
    const int hl   = lane & 15;

    const uint2* Wh4 = (const uint2*)g_Whh;
    float4 acc = make_float4(0.f, 0.f, 0.f, 0.f);
    float dsum = 0.f;

    for (int base = 0; base < cnt; base += 32) {
        int idx = base + lane;
        int c_lane = 0;
        float w_lane = 0.f;
        if (idx < cnt) {
            c_lane = __ldg(&g_ecol[start + idx]);
            float x = ssr + __ldg(&g_sdst[c_lane]);
            x = (x > 0.f) ? x : NEG_SLOPE * x;
            w_lane = __expf(x);
        }
        dsum += w_lane;
        int m = cnt - base; if (m > 32) m = 32;
        int nsteps = (m + 1) >> 1;
        #pragma unroll 4
        for (int j = 0; j < nsteps; j++) {
            int src = 2 * j + half;
            int   c = __shfl_sync(0xFFFFFFFFu, c_lane, src);
            float w = __shfl_sync(0xFFFFFFFFu, w_lane, src);
            uint2 raw = __ldg(&Wh4[(size_t)c * 16 + hl]);
            float2 v0 = __half22float2(*(const __half2*)&raw.x);
            float2 v1 = __half22float2(*(const __half2*)&raw.y);
            acc.x = fmaf(w, v0.x, acc.x);
            acc.y = fmaf(w, v0.y, acc.y);
            acc.z = fmaf(w, v1.x, acc.z);
            acc.w = fmaf(w, v1.y, acc.w);
        }
    }

    #pragma unroll
    for (int o = 16; o > 0; o >>= 1)
        dsum += __shfl_xor_sync(0xFFFFFFFFu, dsum, o);
    const float inv = 1.f / (dsum + 1e-10f);

    acc.x += __shfl_xor_sync(0xFFFFFFFFu, acc.x, 16);
    acc.y += __shfl_xor_sync(0xFFFFFFFFu, acc.y, 16);
    acc.z += __shfl_xor_sync(0xFFFFFFFFu, acc.z, 16);
    acc.w += __shfl_xor_sync(0xFFFFFFFFu, acc.w, 16);

    if (half == 0) {
        acc.x *= inv; acc.y *= inv; acc.z *= inv; acc.w *= inv;
        ((float4*)out)[(size_t)warp * 16 + hl] = acc;
    }

    if (lane == 0) g_count[warp] = 0;   // self-clean for next replay
}

// ---------------------------------------------------------------------------
extern "C" void kernel_launch(void* const* d_in, const int* in_sizes, int n_in,
                              void* d_out, int out_size) {
    const float* h   = (const float*)d_in[0];
    const int*   row = (const int*)d_in[1];
    const int*   col = (const int*)d_in[2];
    const float* W   = (const float*)d_in[3];
    const float* a   = (const float*)d_in[4];
    float*       out = (float*)d_out;

    gemm_hist_kernel<<<GEMM_BLOCKS + HIST_BLOCKS, 256>>>(h, W, a, row);
    scan1_kernel<<<SCAN_NB, SCAN_B>>>();
    scan3_kernel<<<SCAN_NB, SCAN_B>>>();
    scatter_kernel<<<(N_EDGES / 8 + 255) / 256, 256>>>(row, col);
    agg_csr_kernel<<<(N_NODES * 32 + 255) / 256, 256>>>(out);
}